// round 1
// baseline (speedup 1.0000x reference)
#include <cuda_runtime.h>
#include <cuda_bf16.h>

// Problem constants (fixed by the reference)
#define GRID_NX   48
#define GRID_NY   48
#define GRID_NZ   48
#define N_GRID    (GRID_NX * GRID_NY * GRID_NZ)   // 110592
#define SPACING   0.5f
#define A_MAX     800
#define NG        6

// Compacted active-atom SoA (scratch: __device__ globals, no allocation)
__device__ float g_ax[A_MAX];
__device__ float g_ay[A_MAX];
__device__ float g_az[A_MAX];
__device__ float g_c[NG][A_MAX];   // bw * log2(e)  (exp -> exp2 argument scale)
__device__ float g_w[NG][A_MAX];   // aw
__device__ int   g_cnt;

// ---------------------------------------------------------------------------
// Kernel 1: deterministic, order-preserving compaction of active atoms.
// Single warp; warp-ballot prefix scan keeps original atom order, so the
// floating-point accumulation order in kernel 2 is identical every run.
// ---------------------------------------------------------------------------
__global__ void compact_kernel(const float* __restrict__ X,
                               const float* __restrict__ aw,
                               const float* __restrict__ bw,
                               const int*   __restrict__ elements,
                               const int*   __restrict__ C_expand,
                               int n_atoms)
{
    const float LOG2E = 1.4426950408889634f;
    int lane = threadIdx.x;          // blockDim.x == 32
    int base = 0;
    for (int i0 = 0; i0 < n_atoms; i0 += 32) {
        int a = i0 + lane;
        bool act = false;
        if (a < n_atoms)
            act = (elements[a] != 5) && (C_expand[a] == 1);
        unsigned m = __ballot_sync(0xffffffffu, act);
        int pos = base + __popc(m & ((1u << lane) - 1u));
        if (act) {
            g_ax[pos] = X[a * 3 + 0];
            g_ay[pos] = X[a * 3 + 1];
            g_az[pos] = X[a * 3 + 2];
#pragma unroll
            for (int n = 0; n < NG; n++) {
                g_c[n][pos] = bw[a * NG + n] * LOG2E;
                g_w[n][pos] = aw[a * NG + n];
            }
        }
        base += __popc(m);
    }
    if (lane == 0) g_cnt = base;
}

// ---------------------------------------------------------------------------
// Kernel 2: density. One thread per grid point. Atom SoA staged in static
// shared memory (48000 B), broadcast LDS per atom iteration. 6 independent
// EX2 chains per atom + 2 accumulators => enough ILP to saturate the MUFU
// pipe, which is the predicted bottleneck.
// ---------------------------------------------------------------------------
__device__ __forceinline__ float ex2f(float x) {
    float r;
    asm("ex2.approx.f32 %0, %1;" : "=f"(r) : "f"(x));
    return r;
}

__global__ __launch_bounds__(256, 4)
void density_kernel(float* __restrict__ out)
{
    __shared__ float sax[A_MAX];
    __shared__ float say[A_MAX];
    __shared__ float saz[A_MAX];
    __shared__ float sc[NG][A_MAX];
    __shared__ float sw[NG][A_MAX];

    const int cnt = g_cnt;

    for (int i = threadIdx.x; i < cnt; i += blockDim.x) {
        sax[i] = g_ax[i];
        say[i] = g_ay[i];
        saz[i] = g_az[i];
#pragma unroll
        for (int n = 0; n < NG; n++) {
            sc[n][i] = g_c[n][i];
            sw[n][i] = g_w[n][i];
        }
    }
    __syncthreads();

    int g = blockIdx.x * blockDim.x + threadIdx.x;
    if (g >= N_GRID) return;

    // real_grid layout: g = (iz*NY + iy)*NX + ix ; coords = index * 0.5 (exact fp32)
    int ix = g % GRID_NX;
    int iy = (g / GRID_NX) % GRID_NY;
    int iz = g / (GRID_NX * GRID_NY);
    float gx = (float)ix * SPACING;
    float gy = (float)iy * SPACING;
    float gz = (float)iz * SPACING;

    float acc0 = 0.0f;
    float acc1 = 0.0f;

    for (int a = 0; a < cnt; a++) {
        float dx = gx - sax[a];
        float dy = gy - say[a];
        float dz = gz - saz[a];
        float d2 = fmaf(dx, dx, fmaf(dy, dy, dz * dz));

        float e0 = ex2f(d2 * sc[0][a]);
        float e1 = ex2f(d2 * sc[1][a]);
        float e2 = ex2f(d2 * sc[2][a]);
        float e3 = ex2f(d2 * sc[3][a]);
        float e4 = ex2f(d2 * sc[4][a]);
        float e5 = ex2f(d2 * sc[5][a]);

        acc0 = fmaf(sw[0][a], e0, acc0);
        acc1 = fmaf(sw[1][a], e1, acc1);
        acc0 = fmaf(sw[2][a], e2, acc0);
        acc1 = fmaf(sw[3][a], e3, acc1);
        acc0 = fmaf(sw[4][a], e4, acc0);
        acc1 = fmaf(sw[5][a], e5, acc1);
    }

    out[g] = acc0 + acc1;
}

// ---------------------------------------------------------------------------
// Launch. Inputs (metadata order): X[800*3] f32, aw[800*6] f32, bw[800*6] f32,
// elements[800] i32, C_expand[800] i32, real_grid[110592*3] f32 (unused).
// Output: density[110592] f32.
// ---------------------------------------------------------------------------
extern "C" void kernel_launch(void* const* d_in, const int* in_sizes, int n_in,
                              void* d_out, int out_size)
{
    const float* X        = (const float*)d_in[0];
    const float* aw       = (const float*)d_in[1];
    const float* bw       = (const float*)d_in[2];
    const int*   elements = (const int*)d_in[3];
    const int*   C_expand = (const int*)d_in[4];
    float*       out      = (float*)d_out;

    int n_atoms = in_sizes[3];   // element count of `elements`

    compact_kernel<<<1, 32>>>(X, aw, bw, elements, C_expand, n_atoms);

    int threads = 256;
    int blocks  = (N_GRID + threads - 1) / threads;   // 432
    density_kernel<<<blocks, threads>>>(out);
}

// round 2
// speedup vs baseline: 2.5837x; 2.5837x over previous
#include <cuda_runtime.h>
#include <cuda_bf16.h>

// Problem constants (fixed by the reference)
#define GRID_NX   48
#define GRID_NY   48
#define GRID_NZ   48
#define N_GRID    (GRID_NX * GRID_NY * GRID_NZ)   // 110592
#define SPACING   0.5f
#define A_MAX     800
#define NG        6
#define MAX_PAIRS (A_MAX * NG)                    // 4800

// exp2 threshold: drop pair when c*min_d2 < -T  => contribution < 2^-28 * w
#define T_CUT     28.0f

// Tile geometry: 8 x 8 x 4 grid points per block (6*6*12 = 432 blocks)
#define TILE_X 8
#define TILE_Y 8
#define TILE_Z 4
#define NBX (GRID_NX / TILE_X)   // 6
#define NBY (GRID_NY / TILE_Y)   // 6
#define NBZ (GRID_NZ / TILE_Z)   // 12

#define CHUNK 512                // pairs culled per block-chunk

// Pair tables (scratch: __device__ globals, no allocation)
__device__ float4 g_cull[MAX_PAIRS];   // px, py, pz, d2cut
__device__ float4 g_main[MAX_PAIRS];   // px, py, pz, c (= bw * log2e)
__device__ float  g_wtab[MAX_PAIRS];   // aw
__device__ int    g_npairs;

// ---------------------------------------------------------------------------
// Kernel 1: build compacted pair tables. One block, 256 threads.
// Deterministic order-preserving compaction (ballot + cross-warp scan), so
// the accumulation order in kernel 2 is identical on every run.
// ---------------------------------------------------------------------------
__global__ __launch_bounds__(256)
void build_pairs(const float* __restrict__ X,
                 const float* __restrict__ aw,
                 const float* __restrict__ bw,
                 const int*   __restrict__ elements,
                 const int*   __restrict__ C_expand,
                 int n_atoms)
{
    const float LOG2E = 1.4426950408889634f;
    __shared__ int warp_tot[8];
    __shared__ int s_base;

    int tid = threadIdx.x, lane = tid & 31, wid = tid >> 5;
    if (tid == 0) s_base = 0;
    __syncthreads();

    for (int i0 = 0; i0 < n_atoms; i0 += 256) {
        int a = i0 + tid;
        bool act = (a < n_atoms) && (elements[a] != 5) && (C_expand[a] == 1);
        unsigned m = __ballot_sync(0xffffffffu, act);
        if (lane == 0) warp_tot[wid] = __popc(m);
        __syncthreads();

        int wbase = s_base;
        for (int w2 = 0; w2 < wid; w2++) wbase += warp_tot[w2];
        int pos = wbase + __popc(m & ((1u << lane) - 1u));

        if (act) {
            float px = X[a * 3 + 0];
            float py = X[a * 3 + 1];
            float pz = X[a * 3 + 2];
#pragma unroll
            for (int n = 0; n < NG; n++) {
                float c = bw[a * NG + n] * LOG2E;      // c < 0
                float w = aw[a * NG + n];
                int j = pos * NG + n;
                g_cull[j] = make_float4(px, py, pz, T_CUT / (-c));
                g_main[j] = make_float4(px, py, pz, c);
                g_wtab[j] = w;
            }
        }
        __syncthreads();
        if (tid == 0) {
            int tot = 0;
            for (int w2 = 0; w2 < 8; w2++) tot += warp_tot[w2];
            s_base += tot;
        }
        __syncthreads();
    }
    if (tid == 0) g_npairs = s_base * NG;
}

// ---------------------------------------------------------------------------
// Kernel 2: density with per-tile pair culling.
// Block = 64 threads = one 8x8x4 tile; each thread owns 4 consecutive
// x-points (shares dy/dz across them). Pairs processed in chunks of 512:
// cull against tile AABB -> deterministic compaction into shared -> all
// threads accumulate over survivors (broadcast LDS).
// ---------------------------------------------------------------------------
__device__ __forceinline__ float ex2f(float x) {
    float r;
    asm("ex2.approx.f32 %0, %1;" : "=f"(r) : "f"(x));
    return r;
}

__global__ __launch_bounds__(64)
void density_kernel(float* __restrict__ out)
{
    __shared__ float4   s_pc[CHUNK];      // px, py, pz, c
    __shared__ float    s_w[CHUNK];
    __shared__ unsigned s_mask[2][8];
    __shared__ int      s_wtot[2];

    int tid = threadIdx.x, lane = tid & 31, wid = tid >> 5;
    int bid = blockIdx.x;
    int bx = bid % NBX;
    int by = (bid / NBX) % NBY;
    int bz = bid / (NBX * NBY);

    // Tile AABB in real coordinates
    float x_lo = (float)(bx * TILE_X) * SPACING;
    float y_lo = (float)(by * TILE_Y) * SPACING;
    float z_lo = (float)(bz * TILE_Z) * SPACING;
    float x_hi = x_lo + (float)(TILE_X - 1) * SPACING;
    float y_hi = y_lo + (float)(TILE_Y - 1) * SPACING;
    float z_hi = z_lo + (float)(TILE_Z - 1) * SPACING;

    // This thread's 4 x-points: tid -> (xg in {0,1}, ty in 0..7, tz in 0..3)
    int xg = tid & 1;
    int ty = (tid >> 1) & 7;
    int tz = tid >> 4;
    float gx0 = x_lo + (float)(xg * 4) * SPACING;
    float gy  = y_lo + (float)ty * SPACING;
    float gz  = z_lo + (float)tz * SPACING;

    float acc0 = 0.0f, acc1 = 0.0f, acc2 = 0.0f, acc3 = 0.0f;
    int npairs = g_npairs;

    for (int c0 = 0; c0 < npairs; c0 += CHUNK) {
        int cend = npairs - c0;
        if (cend > CHUNK) cend = CHUNK;

        // ---- Phase A: cull this chunk; warp w owns local range [w*256, w*256+256)
        int wtot = 0;
#pragma unroll
        for (int r = 0; r < 8; r++) {
            int j = wid * 256 + r * 32 + lane;   // local index within chunk
            bool sv = false;
            if (j < cend) {
                float4 cd = g_cull[c0 + j];
                float dx = fmaxf(fmaxf(x_lo - cd.x, cd.x - x_hi), 0.0f);
                float dy = fmaxf(fmaxf(y_lo - cd.y, cd.y - y_hi), 0.0f);
                float dz = fmaxf(fmaxf(z_lo - cd.z, cd.z - z_hi), 0.0f);
                float md2 = fmaf(dx, dx, fmaf(dy, dy, dz * dz));
                sv = (md2 <= cd.w);
            }
            unsigned m = __ballot_sync(0xffffffffu, sv);
            if (lane == 0) s_mask[wid][r] = m;
            wtot += __popc(m);
        }
        if (lane == 0) s_wtot[wid] = wtot;
        __syncthreads();

        int base = (wid == 0) ? 0 : s_wtot[0];
        int nsurv = s_wtot[0] + s_wtot[1];

        // ---- Phase B: order-preserving write of survivors into shared
#pragma unroll
        for (int r = 0; r < 8; r++) {
            unsigned m = s_mask[wid][r];
            if (m & (1u << lane)) {
                int pos = base + __popc(m & ((1u << lane) - 1u));
                int j = c0 + wid * 256 + r * 32 + lane;
                s_pc[pos] = g_main[j];
                s_w[pos]  = g_wtab[j];
            }
            base += __popc(m);
        }
        __syncthreads();

        // ---- Phase C: accumulate over survivors (broadcast shared reads)
        for (int s = 0; s < nsurv; s++) {
            float4 p = s_pc[s];
            float  w = s_w[s];
            float dy = gy - p.y;
            float dz = gz - p.z;
            float s2 = fmaf(dy, dy, dz * dz);
            float dx0 = gx0 - p.x;
            float dx1 = dx0 + 0.5f;
            float dx2 = dx0 + 1.0f;
            float dx3 = dx0 + 1.5f;
            float e0 = ex2f(fmaf(dx0, dx0, s2) * p.w);
            float e1 = ex2f(fmaf(dx1, dx1, s2) * p.w);
            float e2 = ex2f(fmaf(dx2, dx2, s2) * p.w);
            float e3 = ex2f(fmaf(dx3, dx3, s2) * p.w);
            acc0 = fmaf(w, e0, acc0);
            acc1 = fmaf(w, e1, acc1);
            acc2 = fmaf(w, e2, acc2);
            acc3 = fmaf(w, e3, acc3);
        }
        __syncthreads();   // protect s_pc/s_mask before next chunk
    }

    // Store 4 consecutive x-points as one float4 (alignment guaranteed: all
    // index terms are multiples of 4)
    int ix0 = bx * TILE_X + xg * 4;
    int iy  = by * TILE_Y + ty;
    int iz  = bz * TILE_Z + tz;
    int g0  = iz * (GRID_NX * GRID_NY) + iy * GRID_NX + ix0;
    *reinterpret_cast<float4*>(out + g0) = make_float4(acc0, acc1, acc2, acc3);
}

// ---------------------------------------------------------------------------
// Launch. Inputs (metadata order): X[800*3] f32, aw[800*6] f32, bw[800*6] f32,
// elements[800] i32, C_expand[800] i32, real_grid[110592*3] f32 (unused).
// Output: density[110592] f32.
// ---------------------------------------------------------------------------
extern "C" void kernel_launch(void* const* d_in, const int* in_sizes, int n_in,
                              void* d_out, int out_size)
{
    const float* X        = (const float*)d_in[0];
    const float* aw       = (const float*)d_in[1];
    const float* bw       = (const float*)d_in[2];
    const int*   elements = (const int*)d_in[3];
    const int*   C_expand = (const int*)d_in[4];
    float*       out      = (float*)d_out;

    int n_atoms = in_sizes[3];

    build_pairs<<<1, 256>>>(X, aw, bw, elements, C_expand, n_atoms);

    density_kernel<<<NBX * NBY * NBZ, 64>>>(out);
}

// round 3
// speedup vs baseline: 3.4965x; 1.3533x over previous
#include <cuda_runtime.h>
#include <cuda_bf16.h>

// Problem constants (fixed by the reference)
#define GRID_NX   48
#define GRID_NY   48
#define GRID_NZ   48
#define N_GRID    (GRID_NX * GRID_NY * GRID_NZ)   // 110592
#define SPACING   0.5f
#define A_MAX     800
#define NG        6
#define MAX_PAIRS (A_MAX * NG)                    // 4800

// Cull threshold: drop pair for a tile when |c|*min_d2 > T  (contribution < 2^-24 * w)
#define T_CUT     24.0f

// Tile geometry: 8 x 8 x 4 grid points per block (432 tiles)
#define TILE_X 8
#define TILE_Y 8
#define TILE_Z 4
#define NBX (GRID_NX / TILE_X)   // 6
#define NBY (GRID_NY / TILE_Y)   // 6
#define NBZ (GRID_NZ / TILE_Z)   // 12
#define N_TILES (NBX * NBY * NBZ)

#define SPLIT  3                 // pair-range partitions (more resident blocks)
#define CHUNK  256               // pairs culled per block-chunk

// Pair tables + partial outputs (scratch: __device__ globals, no allocation)
__device__ float4 g_cull[MAX_PAIRS];    // px, py, pz, d2cut
__device__ float4 g_pcA[MAX_PAIRS];     // px, py, pz, c (= bw * log2e)
__device__ float4 g_pcB[MAX_PAIRS];     // w, q (= 2^(c/2)), c4 (= 0.25c), 0
__device__ int    g_npairs;
__device__ float  g_part[SPLIT][N_GRID];

// ---------------------------------------------------------------------------
// Kernel 1: build compacted pair tables. One block, 256 threads.
// Deterministic order-preserving compaction (ballot + cross-warp scan).
// ---------------------------------------------------------------------------
__global__ __launch_bounds__(256)
void build_pairs(const float* __restrict__ X,
                 const float* __restrict__ aw,
                 const float* __restrict__ bw,
                 const int*   __restrict__ elements,
                 const int*   __restrict__ C_expand,
                 int n_atoms)
{
    const float LOG2E = 1.4426950408889634f;
    __shared__ int warp_tot[8];
    __shared__ int s_base;

    int tid = threadIdx.x, lane = tid & 31, wid = tid >> 5;
    if (tid == 0) s_base = 0;
    __syncthreads();

    for (int i0 = 0; i0 < n_atoms; i0 += 256) {
        int a = i0 + tid;
        bool act = (a < n_atoms) && (elements[a] != 5) && (C_expand[a] == 1);
        unsigned m = __ballot_sync(0xffffffffu, act);
        if (lane == 0) warp_tot[wid] = __popc(m);
        __syncthreads();

        int wbase = s_base;
        for (int w2 = 0; w2 < wid; w2++) wbase += warp_tot[w2];
        int pos = wbase + __popc(m & ((1u << lane) - 1u));

        if (act) {
            float px = X[a * 3 + 0];
            float py = X[a * 3 + 1];
            float pz = X[a * 3 + 2];
#pragma unroll
            for (int n = 0; n < NG; n++) {
                float c = bw[a * NG + n] * LOG2E;      // c < 0
                float w = aw[a * NG + n];
                int j = pos * NG + n;
                g_cull[j] = make_float4(px, py, pz, T_CUT / (-c));
                g_pcA[j]  = make_float4(px, py, pz, c);
                g_pcB[j]  = make_float4(w, exp2f(0.5f * c), 0.25f * c, 0.0f);
            }
        }
        __syncthreads();
        if (tid == 0) {
            int tot = 0;
            for (int w2 = 0; w2 < 8; w2++) tot += warp_tot[w2];
            s_base += tot;
        }
        __syncthreads();
    }
    if (tid == 0) g_npairs = s_base * NG;
}

// ---------------------------------------------------------------------------
// Kernel 2: density partials. blockIdx.x = tile, blockIdx.y = pair partition.
// Block = 64 threads; each thread owns 4 consecutive x-points and uses the
// exp2 recurrence along x: only 2 EX2 per survivor for all 4 points.
// ---------------------------------------------------------------------------
__device__ __forceinline__ float ex2f(float x) {
    float r;
    asm("ex2.approx.f32 %0, %1;" : "=f"(r) : "f"(x));
    return r;
}

__global__ __launch_bounds__(64)
void density_kernel()
{
    __shared__ float4   s_pa[CHUNK];      // px, py, pz, c
    __shared__ float4   s_pb[CHUNK];      // w, q, c4
    __shared__ unsigned s_mask[2][4];
    __shared__ int      s_wtot[2];

    int tid = threadIdx.x, lane = tid & 31, wid = tid >> 5;
    int bid = blockIdx.x;
    int part = blockIdx.y;
    int bx = bid % NBX;
    int by = (bid / NBX) % NBY;
    int bz = bid / (NBX * NBY);

    // Tile AABB in real coordinates
    float x_lo = (float)(bx * TILE_X) * SPACING;
    float y_lo = (float)(by * TILE_Y) * SPACING;
    float z_lo = (float)(bz * TILE_Z) * SPACING;
    float x_hi = x_lo + (float)(TILE_X - 1) * SPACING;
    float y_hi = y_lo + (float)(TILE_Y - 1) * SPACING;
    float z_hi = z_lo + (float)(TILE_Z - 1) * SPACING;

    // This thread's 4 x-points: tid -> (xg in {0,1}, ty in 0..7, tz in 0..3)
    int xg = tid & 1;
    int ty = (tid >> 1) & 7;
    int tz = tid >> 4;
    float gx0 = x_lo + (float)(xg * 4) * SPACING;
    float gy  = y_lo + (float)ty * SPACING;
    float gz  = z_lo + (float)tz * SPACING;

    // This partition's pair range
    int npairs = g_npairs;
    int p_beg = (npairs * part) / SPLIT;
    int p_end = (npairs * (part + 1)) / SPLIT;

    float acc0 = 0.0f, acc1 = 0.0f, acc2 = 0.0f, acc3 = 0.0f;

    for (int c0 = p_beg; c0 < p_end; c0 += CHUNK) {
        int cend = p_end - c0;
        if (cend > CHUNK) cend = CHUNK;

        // ---- Phase A: cull; warp w owns local range [w*128, w*128+128)
        int wtot = 0;
#pragma unroll
        for (int r = 0; r < 4; r++) {
            int j = wid * 128 + r * 32 + lane;    // local index within chunk
            bool sv = false;
            if (j < cend) {
                float4 cd = g_cull[c0 + j];
                float dx = fmaxf(fmaxf(x_lo - cd.x, cd.x - x_hi), 0.0f);
                float dy = fmaxf(fmaxf(y_lo - cd.y, cd.y - y_hi), 0.0f);
                float dz = fmaxf(fmaxf(z_lo - cd.z, cd.z - z_hi), 0.0f);
                float md2 = fmaf(dx, dx, fmaf(dy, dy, dz * dz));
                sv = (md2 <= cd.w);
            }
            unsigned m = __ballot_sync(0xffffffffu, sv);
            if (lane == 0) s_mask[wid][r] = m;
            wtot += __popc(m);
        }
        if (lane == 0) s_wtot[wid] = wtot;
        __syncthreads();

        int base = (wid == 0) ? 0 : s_wtot[0];
        int nsurv = s_wtot[0] + s_wtot[1];

        // ---- Phase B: order-preserving write of survivors into shared
#pragma unroll
        for (int r = 0; r < 4; r++) {
            unsigned m = s_mask[wid][r];
            if (m & (1u << lane)) {
                int pos = base + __popc(m & ((1u << lane) - 1u));
                int j = c0 + wid * 128 + r * 32 + lane;
                s_pa[pos] = g_pcA[j];
                s_pb[pos] = g_pcB[j];
            }
            base += __popc(m);
        }
        __syncthreads();

        // ---- Phase C: accumulate; exp2 recurrence along x.
        // e_i = w * 2^(c*(dx_i^2 + s2)), dx_{i+1} = dx_i + 0.5
        // e_{i+1} = e_i * r_i ;  r_i = 2^(c*dx_i + 0.25c) ;  r_{i+1} = r_i * q
        for (int s = 0; s < nsurv; s++) {
            float4 p = s_pa[s];   // px, py, pz, c
            float4 v = s_pb[s];   // w, q, c4
            float dy = gy - p.y;
            float dz = gz - p.z;
            float s2 = fmaf(dy, dy, dz * dz);
            float dx0 = gx0 - p.x;
            float E0 = ex2f(fmaf(dx0, dx0, s2) * p.w);
            float r0 = ex2f(fmaf(p.w, dx0, v.z));
            float e0 = v.x * E0;
            acc0 += e0;
            float e1 = e0 * r0;
            float r1 = r0 * v.y;
            acc1 += e1;
            float e2 = e1 * r1;
            float r2 = r1 * v.y;
            acc2 += e2;
            float e3 = e2 * r2;
            acc3 += e3;
        }
        __syncthreads();   // protect shared before next chunk
    }

    // Store partial (float4: all index terms are multiples of 4)
    int ix0 = bx * TILE_X + xg * 4;
    int iy  = by * TILE_Y + ty;
    int iz  = bz * TILE_Z + tz;
    int g0  = iz * (GRID_NX * GRID_NY) + iy * GRID_NX + ix0;
    *reinterpret_cast<float4*>(&g_part[part][g0]) =
        make_float4(acc0, acc1, acc2, acc3);
}

// ---------------------------------------------------------------------------
// Kernel 3: deterministic fixed-order sum of the SPLIT partials.
// ---------------------------------------------------------------------------
__global__ __launch_bounds__(256)
void add_kernel(float* __restrict__ out)
{
    int i = blockIdx.x * blockDim.x + threadIdx.x;   // float4 index
    if (i >= N_GRID / 4) return;
    const float4* p0 = reinterpret_cast<const float4*>(g_part[0]);
    const float4* p1 = reinterpret_cast<const float4*>(g_part[1]);
    const float4* p2 = reinterpret_cast<const float4*>(g_part[2]);
    float4 a = p0[i], b = p1[i], c = p2[i];
    float4 r = make_float4((a.x + b.x) + c.x,
                           (a.y + b.y) + c.y,
                           (a.z + b.z) + c.z,
                           (a.w + b.w) + c.w);
    reinterpret_cast<float4*>(out)[i] = r;
}

// ---------------------------------------------------------------------------
// Launch. Inputs (metadata order): X[800*3] f32, aw[800*6] f32, bw[800*6] f32,
// elements[800] i32, C_expand[800] i32, real_grid[110592*3] f32 (unused).
// Output: density[110592] f32.
// ---------------------------------------------------------------------------
extern "C" void kernel_launch(void* const* d_in, const int* in_sizes, int n_in,
                              void* d_out, int out_size)
{
    const float* X        = (const float*)d_in[0];
    const float* aw       = (const float*)d_in[1];
    const float* bw       = (const float*)d_in[2];
    const int*   elements = (const int*)d_in[3];
    const int*   C_expand = (const int*)d_in[4];
    float*       out      = (float*)d_out;

    int n_atoms = in_sizes[3];

    build_pairs<<<1, 256>>>(X, aw, bw, elements, C_expand, n_atoms);

    dim3 grid(N_TILES, SPLIT);
    density_kernel<<<grid, 64>>>();

    int n4 = N_GRID / 4;                       // 27648
    add_kernel<<<(n4 + 255) / 256, 256>>>(out);
}

// round 5
// speedup vs baseline: 4.6474x; 1.3292x over previous
#include <cuda_runtime.h>
#include <cuda_bf16.h>

// Problem constants (fixed by the reference)
#define GRID_NX   48
#define GRID_NY   48
#define GRID_NZ   48
#define N_GRID    (GRID_NX * GRID_NY * GRID_NZ)   // 110592
#define SPACING   0.5f
#define A_MAX     800
#define NG        6
#define MAX_PAIRS (A_MAX * NG)                    // 4800

// Cull threshold: drop pair for a tile when |c|*min_d2 > T  (contribution < 2^-24 * w)
#define T_CUT     24.0f

// Tile geometry: 8 x 8 x 4 grid points per tile (432 tiles)
#define TILE_X 8
#define TILE_Y 8
#define TILE_Z 4
#define NBX (GRID_NX / TILE_X)   // 6
#define NBY (GRID_NY / TILE_Y)   // 6
#define NBZ (GRID_NZ / TILE_Z)   // 12
#define N_TILES (NBX * NBY * NBZ)

#define SPLIT  4                 // pair-range partitions
#define CHUNK  256               // pairs culled per block-chunk

// Pair tables + partial outputs (scratch: __device__ globals, no allocation)
__device__ float4 g_cull[MAX_PAIRS];    // px, py, pz, d2cut (-1 => inactive)
__device__ float4 g_pcA[MAX_PAIRS];     // px, py, pz, c (= bw * log2e)
__device__ float4 g_pcB[MAX_PAIRS];     // w, q (= 2^(c/2)), c4 (= 0.25c), 0
__device__ float  g_part[SPLIT][N_GRID];

__device__ __forceinline__ float ex2f(float x) {
    float r;
    asm("ex2.approx.f32 %0, %1;" : "=f"(r) : "f"(x));
    return r;
}

// ---------------------------------------------------------------------------
// Kernel 1: build pair tables, fully parallel (one thread per pair).
// No compaction: inactive pairs get d2cut = -1 and are dropped by the tile
// cull in kernel 2 (md2 >= 0 > -1). Survivor order == original pair order,
// so accumulation order is deterministic.
// ---------------------------------------------------------------------------
__global__ __launch_bounds__(256)
void build_pairs(const float* __restrict__ X,
                 const float* __restrict__ aw,
                 const float* __restrict__ bw,
                 const int*   __restrict__ elements,
                 const int*   __restrict__ C_expand,
                 int npairs)
{
    const float LOG2E = 1.4426950408889634f;
    int j = blockIdx.x * 256 + threadIdx.x;
    if (j >= npairs) return;
    int a = j / NG;

    bool act = (elements[a] != 5) && (C_expand[a] == 1);
    float c = bw[j] * LOG2E;          // c < 0
    float w = aw[j];
    float px = X[a * 3 + 0];
    float py = X[a * 3 + 1];
    float pz = X[a * 3 + 2];

    g_cull[j] = make_float4(px, py, pz, act ? (T_CUT / (-c)) : -1.0f);
    g_pcA[j]  = make_float4(px, py, pz, c);
    g_pcB[j]  = make_float4(w, ex2f(0.5f * c), 0.25f * c, 0.0f);
}

// ---------------------------------------------------------------------------
// Kernel 2: density partials. blockIdx.x = tile, blockIdx.y = pair partition.
// One warp per block; each thread owns one full x-row (8 points).
// TWO-ANCHOR exp2 recurrence: fresh EX2 anchors at x-index 0 and 4 (each
// point <= 1.5 A from its anchor => anchor magnitude >= 2^-111, no denormal
// flush — this is the round-4 bug fix), one shared ratio chain:
//   r_i = 2^(c*dx_i + 0.25c),  r_{i+1} = r_i * q,  q = 2^(c/2)
// Cost: 3 EX2 + ~30 FMA-pipe ops per survivor for all 8 points.
// ---------------------------------------------------------------------------
__global__ __launch_bounds__(32)
void density_kernel(int npairs)
{
    __shared__ float4 s_pa[CHUNK];    // px, py, pz, c
    __shared__ float4 s_pb[CHUNK];    // w, q, c4

    int lane = threadIdx.x;
    int bid  = blockIdx.x;
    int part = blockIdx.y;
    int bx = bid % NBX;
    int by = (bid / NBX) % NBY;
    int bz = bid / (NBX * NBY);

    // Tile AABB in real coordinates
    float x_lo = (float)(bx * TILE_X) * SPACING;
    float y_lo = (float)(by * TILE_Y) * SPACING;
    float z_lo = (float)(bz * TILE_Z) * SPACING;
    float x_hi = x_lo + (float)(TILE_X - 1) * SPACING;
    float y_hi = y_lo + (float)(TILE_Y - 1) * SPACING;
    float z_hi = z_lo + (float)(TILE_Z - 1) * SPACING;

    // This thread's x-row: lane -> (ty in 0..7, tz in 0..3)
    int ty = lane & 7;
    int tz = lane >> 3;
    float gx0 = x_lo;
    float gy  = y_lo + (float)ty * SPACING;
    float gz  = z_lo + (float)tz * SPACING;

    // This partition's pair range
    int p_beg = (npairs * part) / SPLIT;
    int p_end = (npairs * (part + 1)) / SPLIT;

    float acc[TILE_X];
#pragma unroll
    for (int i = 0; i < TILE_X; i++) acc[i] = 0.0f;

    for (int c0 = p_beg; c0 < p_end; c0 += CHUNK) {
        int cend = p_end - c0;
        if (cend > CHUNK) cend = CHUNK;

        // ---- Fused cull + order-preserving compaction (single warp)
        int nsurv = 0;
#pragma unroll
        for (int r = 0; r < CHUNK / 32; r++) {
            int jl = r * 32 + lane;
            int j  = c0 + jl;
            bool sv = false;
            if (jl < cend) {
                float4 cd = g_cull[j];
                float dx = fmaxf(fmaxf(x_lo - cd.x, cd.x - x_hi), 0.0f);
                float dy = fmaxf(fmaxf(y_lo - cd.y, cd.y - y_hi), 0.0f);
                float dz = fmaxf(fmaxf(z_lo - cd.z, cd.z - z_hi), 0.0f);
                float md2 = fmaf(dx, dx, fmaf(dy, dy, dz * dz));
                sv = (md2 <= cd.w);
            }
            unsigned m = __ballot_sync(0xffffffffu, sv);
            if (sv) {
                int pos = nsurv + __popc(m & ((1u << lane) - 1u));
                s_pa[pos] = g_pcA[j];
                s_pb[pos] = g_pcB[j];
            }
            nsurv += __popc(m);
        }
        __syncwarp();

        // ---- Accumulate with two-anchor recurrence
        for (int s = 0; s < nsurv; s++) {
            float4 p = s_pa[s];   // px, py, pz, c
            float4 v = s_pb[s];   // w, q, c4
            float dy = gy - p.y;
            float dz = gz - p.z;
            float s2 = fmaf(dy, dy, dz * dz);
            float dx0 = gx0 - p.x;
            float dx4 = dx0 + 2.0f;

            // Anchors (direct EX2, each within 1.5 A of its points)
            float e  = v.x * ex2f(fmaf(dx0, dx0, s2) * p.w);   // point 0
            float e4 = v.x * ex2f(fmaf(dx4, dx4, s2) * p.w);   // point 4
            // Ratio chain r_i = 2^(c*dx_i + c/4)
            float r = ex2f(fmaf(p.w, dx0, v.z));

            acc[0] += e;
            e *= r; r *= v.y; acc[1] += e;
            e *= r; r *= v.y; acc[2] += e;
            e *= r; r *= v.y; acc[3] += e;
            r *= v.y;                       // r now = r4
            acc[4] += e4;
            e4 *= r; r *= v.y; acc[5] += e4;
            e4 *= r; r *= v.y; acc[6] += e4;
            e4 *= r;           acc[7] += e4;
        }
        __syncwarp();   // protect shared before next chunk
    }

    // Store partial: one x-row = two float4s (base is 8-aligned)
    int ix0 = bx * TILE_X;
    int iy  = by * TILE_Y + ty;
    int iz  = bz * TILE_Z + tz;
    int g0  = iz * (GRID_NX * GRID_NY) + iy * GRID_NX + ix0;
    *reinterpret_cast<float4*>(&g_part[part][g0]) =
        make_float4(acc[0], acc[1], acc[2], acc[3]);
    *reinterpret_cast<float4*>(&g_part[part][g0 + 4]) =
        make_float4(acc[4], acc[5], acc[6], acc[7]);
}

// ---------------------------------------------------------------------------
// Kernel 3: deterministic fixed-order sum of the SPLIT partials.
// ---------------------------------------------------------------------------
__global__ __launch_bounds__(256)
void add_kernel(float* __restrict__ out)
{
    int i = blockIdx.x * blockDim.x + threadIdx.x;   // float4 index
    if (i >= N_GRID / 4) return;
    const float4* p0 = reinterpret_cast<const float4*>(g_part[0]);
    const float4* p1 = reinterpret_cast<const float4*>(g_part[1]);
    const float4* p2 = reinterpret_cast<const float4*>(g_part[2]);
    const float4* p3 = reinterpret_cast<const float4*>(g_part[3]);
    float4 a = p0[i], b = p1[i], c = p2[i], d = p3[i];
    float4 r = make_float4(((a.x + b.x) + c.x) + d.x,
                           ((a.y + b.y) + c.y) + d.y,
                           ((a.z + b.z) + c.z) + d.z,
                           ((a.w + b.w) + c.w) + d.w);
    reinterpret_cast<float4*>(out)[i] = r;
}

// ---------------------------------------------------------------------------
// Launch. Inputs (metadata order): X[800*3] f32, aw[800*6] f32, bw[800*6] f32,
// elements[800] i32, C_expand[800] i32, real_grid[110592*3] f32 (unused).
// Output: density[110592] f32.
// ---------------------------------------------------------------------------
extern "C" void kernel_launch(void* const* d_in, const int* in_sizes, int n_in,
                              void* d_out, int out_size)
{
    const float* X        = (const float*)d_in[0];
    const float* aw       = (const float*)d_in[1];
    const float* bw       = (const float*)d_in[2];
    const int*   elements = (const int*)d_in[3];
    const int*   C_expand = (const int*)d_in[4];
    float*       out      = (float*)d_out;

    int n_atoms = in_sizes[3];
    int npairs  = n_atoms * NG;

    build_pairs<<<(npairs + 255) / 256, 256>>>(X, aw, bw, elements, C_expand,
                                               npairs);

    dim3 grid(N_TILES, SPLIT);
    density_kernel<<<grid, 32>>>(npairs);

    int n4 = N_GRID / 4;                       // 27648
    add_kernel<<<(n4 + 255) / 256, 256>>>(out);
}

// round 6
// speedup vs baseline: 5.1809x; 1.1148x over previous
#include <cuda_runtime.h>
#include <cuda_bf16.h>

// Problem constants (fixed by the reference)
#define GRID_NX   48
#define GRID_NY   48
#define GRID_NZ   48
#define N_GRID    (GRID_NX * GRID_NY * GRID_NZ)   // 110592
#define SPACING   0.5f
#define A_MAX     800
#define NG        6
#define MAX_PAIRS (A_MAX * NG)                    // 4800

// Cull threshold: drop pair for a tile when |c|*min_d2 > T  (contribution < 2^-24 * w)
#define T_CUT     24.0f

// Tile geometry: 8 x 8 x 4 grid points per tile (432 tiles)
#define TILE_X 8
#define TILE_Y 8
#define TILE_Z 4
#define NBX (GRID_NX / TILE_X)   // 6
#define NBY (GRID_NY / TILE_Y)   // 6
#define NBZ (GRID_NZ / TILE_Z)   // 12
#define N_TILES (NBX * NBY * NBZ)

#define NWARP  4                 // pair-range partitions (one warp each)
#define CHUNK  256               // pairs culled per warp-chunk

// Pair tables (scratch: __device__ globals, no allocation)
__device__ float4 g_cull[MAX_PAIRS];    // px, py, pz, d2cut (-1 => inactive)
__device__ float4 g_pcA[MAX_PAIRS];     // px, py, pz, c (= bw * log2e)
__device__ float4 g_pcB[MAX_PAIRS];     // w, q (= 2^(c/2)), c4 (= 0.25c), 0

__device__ __forceinline__ float ex2f(float x) {
    float r;
    asm("ex2.approx.f32 %0, %1;" : "=f"(r) : "f"(x));
    return r;
}

// ---------------------------------------------------------------------------
// Kernel 1: build pair tables, fully parallel (one thread per pair).
// Inactive pairs get d2cut = -1 and are dropped by the tile cull in kernel 2
// (md2 >= 0 > -1). Survivor order == original pair order => deterministic.
// ---------------------------------------------------------------------------
__global__ __launch_bounds__(128)
void build_pairs(const float* __restrict__ X,
                 const float* __restrict__ aw,
                 const float* __restrict__ bw,
                 const int*   __restrict__ elements,
                 const int*   __restrict__ C_expand,
                 int npairs)
{
    const float LOG2E = 1.4426950408889634f;
    int j = blockIdx.x * 128 + threadIdx.x;
    if (j >= npairs) return;
    int a = j / NG;

    bool act = (elements[a] != 5) && (C_expand[a] == 1);
    float c = bw[j] * LOG2E;          // c < 0
    float w = aw[j];
    float px = X[a * 3 + 0];
    float py = X[a * 3 + 1];
    float pz = X[a * 3 + 2];

    g_cull[j] = make_float4(px, py, pz, act ? (T_CUT / (-c)) : -1.0f);
    g_pcA[j]  = make_float4(px, py, pz, c);
    g_pcB[j]  = make_float4(w, ex2f(0.5f * c), 0.25f * c, 0.0f);
}

// ---------------------------------------------------------------------------
// Kernel 2: density, fused. One 128-thread block per tile; warp w handles
// pair quarter w independently (cull + accumulate, same order as the previous
// SPLIT scheme), then a deterministic fixed-order intra-block reduction
// (((w0+w1)+w2)+w3) replaces the old add_kernel. Direct write to out.
//
// Per-warp math: each lane owns one x-row (8 points); TWO-ANCHOR exp2
// recurrence (anchors at x-index 0 and 4, each point <= 1.5 A from its
// anchor => anchor magnitude >= 2^-111, no denormal flush):
//   r_i = 2^(c*dx_i + 0.25c),  r_{i+1} = r_i * q,  q = 2^(c/2)
// ---------------------------------------------------------------------------
__global__ __launch_bounds__(128)
void density_kernel(int npairs, float* __restrict__ out)
{
    __shared__ float4 s_pa[NWARP][CHUNK];     // px, py, pz, c
    __shared__ float4 s_pb[NWARP][CHUNK];     // w, q, c4
    __shared__ float  s_acc[NWARP][32][TILE_X + 1];   // +1: bank padding

    int tid  = threadIdx.x;
    int lane = tid & 31;
    int wid  = tid >> 5;
    int bid  = blockIdx.x;
    int bx = bid % NBX;
    int by = (bid / NBX) % NBY;
    int bz = bid / (NBX * NBY);

    // Tile AABB in real coordinates
    float x_lo = (float)(bx * TILE_X) * SPACING;
    float y_lo = (float)(by * TILE_Y) * SPACING;
    float z_lo = (float)(bz * TILE_Z) * SPACING;
    float x_hi = x_lo + (float)(TILE_X - 1) * SPACING;
    float y_hi = y_lo + (float)(TILE_Y - 1) * SPACING;
    float z_hi = z_lo + (float)(TILE_Z - 1) * SPACING;

    // This lane's x-row: lane -> (ty in 0..7, tz in 0..3)
    int ty = lane & 7;
    int tz = lane >> 3;
    float gx0 = x_lo;
    float gy  = y_lo + (float)ty * SPACING;
    float gz  = z_lo + (float)tz * SPACING;

    // This warp's pair range (== old SPLIT partitions => same sum order)
    int p_beg = (npairs * wid) / NWARP;
    int p_end = (npairs * (wid + 1)) / NWARP;

    float acc[TILE_X];
#pragma unroll
    for (int i = 0; i < TILE_X; i++) acc[i] = 0.0f;

    for (int c0 = p_beg; c0 < p_end; c0 += CHUNK) {
        int cend = p_end - c0;
        if (cend > CHUNK) cend = CHUNK;

        // ---- Fused cull + order-preserving compaction (per warp)
        int nsurv = 0;
#pragma unroll
        for (int r = 0; r < CHUNK / 32; r++) {
            int jl = r * 32 + lane;
            int j  = c0 + jl;
            bool sv = false;
            if (jl < cend) {
                float4 cd = g_cull[j];
                float dx = fmaxf(fmaxf(x_lo - cd.x, cd.x - x_hi), 0.0f);
                float dy = fmaxf(fmaxf(y_lo - cd.y, cd.y - y_hi), 0.0f);
                float dz = fmaxf(fmaxf(z_lo - cd.z, cd.z - z_hi), 0.0f);
                float md2 = fmaf(dx, dx, fmaf(dy, dy, dz * dz));
                sv = (md2 <= cd.w);
            }
            unsigned m = __ballot_sync(0xffffffffu, sv);
            if (sv) {
                int pos = nsurv + __popc(m & ((1u << lane) - 1u));
                s_pa[wid][pos] = g_pcA[j];
                s_pb[wid][pos] = g_pcB[j];
            }
            nsurv += __popc(m);
        }
        __syncwarp();

        // ---- Accumulate with two-anchor recurrence
        for (int s = 0; s < nsurv; s++) {
            float4 p = s_pa[wid][s];   // px, py, pz, c
            float4 v = s_pb[wid][s];   // w, q, c4
            float dy = gy - p.y;
            float dz = gz - p.z;
            float s2 = fmaf(dy, dy, dz * dz);
            float dx0 = gx0 - p.x;
            float dx4 = dx0 + 2.0f;

            float e  = v.x * ex2f(fmaf(dx0, dx0, s2) * p.w);   // anchor @ x0
            float e4 = v.x * ex2f(fmaf(dx4, dx4, s2) * p.w);   // anchor @ x4
            float r  = ex2f(fmaf(p.w, dx0, v.z));              // ratio chain

            acc[0] += e;
            e *= r; r *= v.y; acc[1] += e;
            e *= r; r *= v.y; acc[2] += e;
            e *= r; r *= v.y; acc[3] += e;
            r *= v.y;                       // r now = r4
            acc[4] += e4;
            e4 *= r; r *= v.y; acc[5] += e4;
            e4 *= r; r *= v.y; acc[6] += e4;
            e4 *= r;           acc[7] += e4;
        }
        __syncwarp();   // protect this warp's shared chunk before refill
    }

    // ---- Deposit per-warp accumulators
#pragma unroll
    for (int i = 0; i < TILE_X; i++)
        s_acc[wid][lane][i] = acc[i];
    __syncthreads();

    // ---- Deterministic fixed-order reduction + direct store.
    // Thread t = l*4 + k handles x-indices {2k, 2k+1} of row l.
    int l = tid >> 2;
    int k = tid & 3;
    int rty = l & 7;
    int rtz = l >> 3;
    int g0 = (bz * TILE_Z + rtz) * (GRID_NX * GRID_NY)
           + (by * TILE_Y + rty) * GRID_NX
           + bx * TILE_X + 2 * k;

    float r0 = ((s_acc[0][l][2 * k]     + s_acc[1][l][2 * k])
              +  s_acc[2][l][2 * k])    + s_acc[3][l][2 * k];
    float r1 = ((s_acc[0][l][2 * k + 1] + s_acc[1][l][2 * k + 1])
              +  s_acc[2][l][2 * k + 1]) + s_acc[3][l][2 * k + 1];
    *reinterpret_cast<float2*>(out + g0) = make_float2(r0, r1);
}

// ---------------------------------------------------------------------------
// Launch. Inputs (metadata order): X[800*3] f32, aw[800*6] f32, bw[800*6] f32,
// elements[800] i32, C_expand[800] i32, real_grid[110592*3] f32 (unused).
// Output: density[110592] f32.
// ---------------------------------------------------------------------------
extern "C" void kernel_launch(void* const* d_in, const int* in_sizes, int n_in,
                              void* d_out, int out_size)
{
    const float* X        = (const float*)d_in[0];
    const float* aw       = (const float*)d_in[1];
    const float* bw       = (const float*)d_in[2];
    const int*   elements = (const int*)d_in[3];
    const int*   C_expand = (const int*)d_in[4];
    float*       out      = (float*)d_out;

    int n_atoms = in_sizes[3];
    int npairs  = n_atoms * NG;

    build_pairs<<<(npairs + 127) / 128, 128>>>(X, aw, bw, elements, C_expand,
                                               npairs);

    density_kernel<<<N_TILES, 128>>>(npairs, out);
}